// round 4
// baseline (speedup 1.0000x reference)
#include <cuda_runtime.h>
#include <cuda_bf16.h>

#define B_TOT 8192
#define T_LEN 60

// global scratch: r1 (then overwritten by r2) in [t][j][b] layout
__device__ float g_r1[(size_t)T_LEN * 64 * B_TOT];

__device__ __forceinline__ void fma2(unsigned long long &d, unsigned long long a, unsigned long long b) {
    asm("fma.rn.f32x2 %0, %1, %2, %0;" : "+l"(d) : "l"(a), "l"(b));
}
__device__ __forceinline__ unsigned long long dup2(float x) {
    unsigned long long r; asm("mov.b64 %0, {%1, %1};" : "=l"(r) : "f"(x)); return r;
}
__device__ __forceinline__ unsigned long long pk2(float x, float y) {
    unsigned long long r; asm("mov.b64 %0, {%1, %2};" : "=l"(r) : "f"(x), "f"(y)); return r;
}
__device__ __forceinline__ float2 unpk(unsigned long long v) {
    float2 f; asm("mov.b64 {%0, %1}, %2;" : "=f"(f.x), "=f"(f.y) : "l"(v)); return f;
}
__device__ __forceinline__ float ex2a(float x) { float r; asm("ex2.approx.f32 %0, %1;" : "=f"(r) : "f"(x)); return r; }
__device__ __forceinline__ float rcpa(float x) { float r; asm("rcp.approx.f32 %0, %1;" : "=f"(r) : "f"(x)); return r; }
__device__ __forceinline__ float sigm(float x)  { return rcpa(1.0f + ex2a(-1.4426950408889634f * x)); }
__device__ __forceinline__ float tanha(float x) { return fmaf(2.0f, rcpa(1.0f + ex2a(-2.8853900817779268f * x)), -1.0f); }

// One LSTM layer, 64 hidden units, 64 batches per block (grid 128).
// KIN = 80 (LSTM1: [tanh(main@Wi^T+bi), mem], time reversed) or 64 (LSTM2: r1).
// act2 smem rows (stride 66 ull) hold duplicated (v,v) activations; k<KIN input, k>=KIN recurrent h.
template<int KIN>
__global__ void __launch_bounds__(256, 1) lstm_kernel(
    const float* __restrict__ inputs_main,
    const float* __restrict__ inputs_aux,
    const float* __restrict__ rnn1_mem,
    const float* __restrict__ Wi, const float* __restrict__ bi,
    const float* __restrict__ Whx1, const float* __restrict__ bhx1,  // Ws1/bs1 | Wt1/bt1
    const float* __restrict__ Whx2, const float* __restrict__ bhx2,  // Ws2/bs2 | Wt2/bt2
    const float* __restrict__ Wih, const float* __restrict__ Whh,
    const float* __restrict__ bih, const float* __restrict__ bhh,
    const float* __restrict__ Wso, const float* __restrict__ bso,
    float* __restrict__ out_sfc)
{
    constexpr bool IS1 = (KIN == 80);
    constexpr int KTOT = KIN + 64;
    constexpr int AST = 66; // act2 row stride in ull (padded vs 64 to reduce bank conflicts)

    extern __shared__ char smem_raw[];
    float* wAf = (float*)smem_raw;                       // [KTOT][32 pairs][4] gates i,f
    float* wBf = wAf + KTOT * 128;                       // gates g,o
    unsigned long long* act2 = (unsigned long long*)(wBf + KTOT * 128); // [KTOT][AST]
    float* bias = (float*)(act2 + KTOT * AST);           // 256
    float* sWi  = bias + 256;                            // 256 (LSTM1)
    float* sbi  = sWi + 256;                             // 64  (LSTM1)

    const int tid = threadIdx.x;
    const int pp  = tid & 15;     // pair group: pairs pp and pp+16 -> j = 2*(pp+16*pj)+e
    const int bg  = tid >> 4;     // batch group 0..15 -> batches bg*4..bg*4+3
    const int b0  = blockIdx.x * 64;

    // ---- fill reordered weights: wA[k][p] = (Wi[2p][k],Wi[2p+1][k],Wf[2p][k],Wf[2p+1][k]); wB = g,o
    for (int idx = tid; idx < KTOT * 256; idx += 256) {
        int k = idx >> 8, r = idx & 255;
        int half = r >> 7, rr = r & 127;
        int p = rr >> 2, q = rr & 3;
        int row = half * 128 + (q >> 1) * 64 + 2 * p + (q & 1);
        float v = (k < KIN) ? Wih[row * KIN + k] : Whh[row * 64 + (k - KIN)];
        (half ? wBf : wAf)[k * 128 + rr] = v;
    }
    bias[tid] = bih[tid] + bhh[tid];
    if (IS1) {
        sWi[tid] = Wi[tid];
        if (tid < 64) sbi[tid] = bi[tid];
    }
    __syncthreads();

    // ---- initial h0 (dup into act2 recurrent slots) and c0 (registers)
    float cst[2][4][2]; // [pj][b][e]
    #pragma unroll
    for (int pj = 0; pj < 2; pj++)
    #pragma unroll
    for (int e = 0; e < 2; e++) {
        const int j = 2 * (pp + 16 * pj) + e;
        #pragma unroll
        for (int b = 0; b < 4; b++) {
            const int bb = b0 + bg * 4 + b;
            float h0, c0;
            if (IS1) {
                float a0 = inputs_aux[bb * 3 + 0], a1 = inputs_aux[bb * 3 + 1], a2 = inputs_aux[bb * 3 + 2];
                h0 = tanha(a0 * Whx1[j * 3 + 0] + a1 * Whx1[j * 3 + 1] + a2 * Whx1[j * 3 + 2] + bhx1[j]);
                c0 = tanha(a0 * Whx2[j * 3 + 0] + a1 * Whx2[j * 3 + 1] + a2 * Whx2[j * 3 + 2] + bhx2[j]);
            } else {
                float toa = inputs_aux[bb * 3 + 1];
                h0 = toa * Whx1[j] + bhx1[j];
                c0 = toa * Whx2[j] + bhx2[j];
            }
            cst[pj][b][e] = c0;
            act2[(KIN + j) * AST + bg * 4 + b] = dup2(h0);
        }
    }

    // ---- phase A for the first step
    const int bA = tid & 63, kq = tid >> 6;
    {
        const int tf = IS1 ? (T_LEN - 1) : 0;
        if (IS1) {
            const float4 mv = *(const float4*)(inputs_main + ((size_t)(b0 + bA) * T_LEN + tf) * 4);
            #pragma unroll
            for (int kk = 0; kk < 16; kk++) {
                int k = kq * 16 + kk;
                float v = tanha(mv.x * sWi[k * 4] + mv.y * sWi[k * 4 + 1] + mv.z * sWi[k * 4 + 2] + mv.w * sWi[k * 4 + 3] + sbi[k]);
                act2[k * AST + bA] = dup2(v);
            }
            const float4 mm = *(const float4*)(rnn1_mem + (((size_t)(b0 + bA) * T_LEN + tf) * 16 + kq * 4));
            act2[(64 + kq * 4 + 0) * AST + bA] = dup2(mm.x);
            act2[(64 + kq * 4 + 1) * AST + bA] = dup2(mm.y);
            act2[(64 + kq * 4 + 2) * AST + bA] = dup2(mm.z);
            act2[(64 + kq * 4 + 3) * AST + bA] = dup2(mm.w);
        } else {
            #pragma unroll
            for (int it = 0; it < 16; it++) {
                int j = it * 4 + kq;
                act2[j * AST + bA] = dup2(g_r1[((size_t)0 * 64 + j) * B_TOT + b0 + bA]);
            }
        }
    }
    __syncthreads();

    // ---- time loop
    for (int s = 0; s < T_LEN; s++) {
        const int t = IS1 ? (T_LEN - 1 - s) : s;

        unsigned long long acc[4][2][4];
        #pragma unroll
        for (int pj = 0; pj < 2; pj++) {
            const int j0 = 2 * (pp + 16 * pj);
            #pragma unroll
            for (int g = 0; g < 4; g++) {
                unsigned long long bz = pk2(bias[g * 64 + j0], bias[g * 64 + j0 + 1]);
                #pragma unroll
                for (int b = 0; b < 4; b++) acc[g][pj][b] = bz;
            }
        }

        const float* wap = wAf + pp * 4;
        const float* wbp = wBf + pp * 4;
        const unsigned long long* ap = act2 + bg * 4;
        #pragma unroll 4
        for (int k = 0; k < KTOT; k++) {
            ulonglong2 wa0 = *(const ulonglong2*)(wap + k * 128);        // pair pp   : (i, f)
            ulonglong2 wa1 = *(const ulonglong2*)(wap + k * 128 + 64);   // pair pp+16: (i, f)
            ulonglong2 wb0 = *(const ulonglong2*)(wbp + k * 128);        // pair pp   : (g, o)
            ulonglong2 wb1 = *(const ulonglong2*)(wbp + k * 128 + 64);   // pair pp+16: (g, o)
            ulonglong2 a01 = *(const ulonglong2*)(ap + k * AST);
            ulonglong2 a23 = *(const ulonglong2*)(ap + k * AST + 2);
            unsigned long long av[4] = {a01.x, a01.y, a23.x, a23.y};
            #pragma unroll
            for (int b = 0; b < 4; b++) {
                fma2(acc[0][0][b], wa0.x, av[b]);
                fma2(acc[1][0][b], wa0.y, av[b]);
                fma2(acc[2][0][b], wb0.x, av[b]);
                fma2(acc[3][0][b], wb0.y, av[b]);
                fma2(acc[0][1][b], wa1.x, av[b]);
                fma2(acc[1][1][b], wa1.y, av[b]);
                fma2(acc[2][1][b], wb1.x, av[b]);
                fma2(acc[3][1][b], wb1.y, av[b]);
            }
        }
        __syncthreads();

        // prefetch next-step inputs (global) to hide latency under epilogue math
        const bool havenext = (s < T_LEN - 1);
        const int t2 = IS1 ? (t - 1) : (t + 1);
        float4 mv, mm;
        float rv[16];
        if (havenext) {
            if (IS1) {
                mv = *(const float4*)(inputs_main + ((size_t)(b0 + bA) * T_LEN + t2) * 4);
                mm = *(const float4*)(rnn1_mem + (((size_t)(b0 + bA) * T_LEN + t2) * 16 + kq * 4));
            } else {
                #pragma unroll
                for (int it = 0; it < 16; it++) {
                    int j = it * 4 + kq;
                    rv[it] = g_r1[((size_t)t2 * 64 + j) * B_TOT + b0 + bA];
                }
            }
        }

        // epilogue: gate activations, cell update
        float hv[2][2][4]; // [pj][e][b]
        #pragma unroll
        for (int pj = 0; pj < 2; pj++)
        #pragma unroll
        for (int b = 0; b < 4; b++) {
            float2 gi = unpk(acc[0][pj][b]);
            float2 gf = unpk(acc[1][pj][b]);
            float2 gg = unpk(acc[2][pj][b]);
            float2 go = unpk(acc[3][pj][b]);
            {
                float cc = sigm(gf.x) * cst[pj][b][0] + sigm(gi.x) * tanha(gg.x);
                cst[pj][b][0] = cc;
                hv[pj][0][b] = sigm(go.x) * tanha(cc);
            }
            {
                float cc = sigm(gf.y) * cst[pj][b][1] + sigm(gi.y) * tanha(gg.y);
                cst[pj][b][1] = cc;
                hv[pj][1][b] = sigm(go.y) * tanha(cc);
            }
        }
        // write h: dup into act2 recurrent slots + transposed global (r1 / r2)
        #pragma unroll
        for (int pj = 0; pj < 2; pj++)
        #pragma unroll
        for (int e = 0; e < 2; e++) {
            const int j = 2 * (pp + 16 * pj) + e;
            #pragma unroll
            for (int b = 0; b < 4; b++)
                act2[(KIN + j) * AST + bg * 4 + b] = dup2(hv[pj][e][b]);
            *(float4*)(g_r1 + ((size_t)t * 64 + j) * B_TOT + b0 + bg * 4) =
                make_float4(hv[pj][e][0], hv[pj][e][1], hv[pj][e][2], hv[pj][e][3]);
        }

        // phase A: fill input slots for next step
        if (havenext) {
            if (IS1) {
                #pragma unroll
                for (int kk = 0; kk < 16; kk++) {
                    int k = kq * 16 + kk;
                    float v = tanha(mv.x * sWi[k * 4] + mv.y * sWi[k * 4 + 1] + mv.z * sWi[k * 4 + 2] + mv.w * sWi[k * 4 + 3] + sbi[k]);
                    act2[k * AST + bA] = dup2(v);
                }
                act2[(64 + kq * 4 + 0) * AST + bA] = dup2(mm.x);
                act2[(64 + kq * 4 + 1) * AST + bA] = dup2(mm.y);
                act2[(64 + kq * 4 + 2) * AST + bA] = dup2(mm.z);
                act2[(64 + kq * 4 + 3) * AST + bA] = dup2(mm.w);
            } else {
                #pragma unroll
                for (int it = 0; it < 16; it++) {
                    int j = it * 4 + kq;
                    act2[j * AST + bA] = dup2(rv[it]);
                }
            }
        }
        __syncthreads();
    }

    // ---- out_sfc = hL @ Wso^T + bso (LSTM2 only; final h sits in act2 recurrent slots)
    if (!IS1) {
        if (tid < 64) {
            const float* a2f = (const float*)act2;
            float s0 = bso[0], s1 = bso[1], s2 = bso[2];
            #pragma unroll 8
            for (int j = 0; j < 64; j++) {
                float h = a2f[((64 + j) * AST + tid) * 2];
                s0 += Wso[0 * 64 + j] * h;
                s1 += Wso[1 * 64 + j] * h;
                s2 += Wso[2 * 64 + j] * h;
            }
            out_sfc[(size_t)(b0 + tid) * 3 + 0] = s0;
            out_sfc[(size_t)(b0 + tid) * 3 + 1] = s1;
            out_sfc[(size_t)(b0 + tid) * 3 + 2] = s2;
        }
    }
}

// lat = r2 @ Wl^T + bl ; new_mem = lat ; out = lat @ Wo^T + bo
__global__ void __launch_bounds__(256) head_kernel(
    const float* __restrict__ Wl, const float* __restrict__ bl,
    const float* __restrict__ Wo, const float* __restrict__ bo,
    float* __restrict__ out, float* __restrict__ newmem)
{
    __shared__ float sWl[1024], sbl[16], sWo[64], sbo[4];
    const int tid = threadIdx.x;
    for (int i = tid; i < 1024; i += 256) sWl[i] = Wl[i];
    if (tid < 16) sbl[tid] = bl[tid];
    if (tid < 64) sWo[tid] = Wo[tid];
    if (tid < 4)  sbo[tid] = bo[tid];
    __syncthreads();

    const int t = blockIdx.x;
    const size_t b = (size_t)blockIdx.y * 256 + tid;

    float v[64];
    #pragma unroll
    for (int j = 0; j < 64; j++)
        v[j] = g_r1[((size_t)t * 64 + j) * B_TOT + b];

    float lat[16];
    #pragma unroll
    for (int m = 0; m < 16; m++) {
        float s = sbl[m];
        #pragma unroll
        for (int j = 0; j < 64; j++) s += sWl[m * 64 + j] * v[j];
        lat[m] = s;
    }
    float4* nm = (float4*)(newmem + (b * T_LEN + t) * 16);
    nm[0] = make_float4(lat[0], lat[1], lat[2], lat[3]);
    nm[1] = make_float4(lat[4], lat[5], lat[6], lat[7]);
    nm[2] = make_float4(lat[8], lat[9], lat[10], lat[11]);
    nm[3] = make_float4(lat[12], lat[13], lat[14], lat[15]);

    float o[4];
    #pragma unroll
    for (int y = 0; y < 4; y++) {
        float s = sbo[y];
        #pragma unroll
        for (int m = 0; m < 16; m++) s += sWo[y * 16 + m] * lat[m];
        o[y] = s;
    }
    *(float4*)(out + (b * T_LEN + t) * 4) = make_float4(o[0], o[1], o[2], o[3]);
}

extern "C" void kernel_launch(void* const* d_in, const int* in_sizes, int n_in,
                              void* d_out, int out_size) {
    const float* inputs_main = (const float*)d_in[0];
    const float* inputs_aux  = (const float*)d_in[1];
    const float* rnn1_mem    = (const float*)d_in[2];
    const float* Wi   = (const float*)d_in[3];
    const float* bi   = (const float*)d_in[4];
    const float* Ws1  = (const float*)d_in[5];
    const float* bs1  = (const float*)d_in[6];
    const float* Ws2  = (const float*)d_in[7];
    const float* bs2  = (const float*)d_in[8];
    const float* Wt1  = (const float*)d_in[9];
    const float* bt1  = (const float*)d_in[10];
    const float* Wt2  = (const float*)d_in[11];
    const float* bt2  = (const float*)d_in[12];
    const float* Wih1 = (const float*)d_in[13];
    const float* Whh1 = (const float*)d_in[14];
    const float* bih1 = (const float*)d_in[15];
    const float* bhh1 = (const float*)d_in[16];
    const float* Wih2 = (const float*)d_in[17];
    const float* Whh2 = (const float*)d_in[18];
    const float* bih2 = (const float*)d_in[19];
    const float* bhh2 = (const float*)d_in[20];
    const float* Wl   = (const float*)d_in[21];
    const float* bl   = (const float*)d_in[22];
    const float* Wo   = (const float*)d_in[23];
    const float* bo   = (const float*)d_in[24];
    const float* Wso  = (const float*)d_in[25];
    const float* bso  = (const float*)d_in[26];

    float* out     = (float*)d_out;
    float* out_sfc = out + (size_t)B_TOT * T_LEN * 4;
    float* newmem  = out_sfc + (size_t)B_TOT * 3;

    const int smem1 = 144 * 128 * 2 * 4 + 144 * 66 * 8 + (256 + 256 + 64) * 4;
    const int smem2 = 128 * 128 * 2 * 4 + 128 * 66 * 8 + (256 + 256 + 64) * 4;
    cudaFuncSetAttribute((const void*)lstm_kernel<80>, cudaFuncAttributeMaxDynamicSharedMemorySize, smem1);
    cudaFuncSetAttribute((const void*)lstm_kernel<64>, cudaFuncAttributeMaxDynamicSharedMemorySize, smem2);

    lstm_kernel<80><<<128, 256, smem1>>>(inputs_main, inputs_aux, rnn1_mem, Wi, bi,
                                         Ws1, bs1, Ws2, bs2, Wih1, Whh1, bih1, bhh1,
                                         nullptr, nullptr, nullptr);
    lstm_kernel<64><<<128, 256, smem2>>>(inputs_main, inputs_aux, rnn1_mem, Wi, bi,
                                         Wt1, bt1, Wt2, bt2, Wih2, Whh2, bih2, bhh2,
                                         Wso, bso, out_sfc);
    head_kernel<<<dim3(T_LEN, B_TOT / 256), 256>>>(Wl, bl, Wo, bo, out, newmem);
}

// round 5
// speedup vs baseline: 1.2388x; 1.2388x over previous
#include <cuda_runtime.h>
#include <cuda_bf16.h>

#define B_TOT 8192
#define T_LEN 60

typedef unsigned long long ull;

// global scratch: r1 (then overwritten by r2) in [t][j][b] layout
__device__ float g_r1[(size_t)T_LEN * 64 * B_TOT];

__device__ __forceinline__ void fma2(ull &d, ull a, ull b) {
    asm("fma.rn.f32x2 %0, %1, %2, %0;" : "+l"(d) : "l"(a), "l"(b));
}
__device__ __forceinline__ ull dup2(float x) {
    ull r; asm("mov.b64 %0, {%1, %1};" : "=l"(r) : "f"(x)); return r;
}
__device__ __forceinline__ ull pk2(float x, float y) {
    ull r; asm("mov.b64 %0, {%1, %2};" : "=l"(r) : "f"(x), "f"(y)); return r;
}
__device__ __forceinline__ float2 unpk(ull v) {
    float2 f; asm("mov.b64 {%0, %1}, %2;" : "=f"(f.x), "=f"(f.y) : "l"(v)); return f;
}
__device__ __forceinline__ float tanha(float x) {
    float r; asm("tanh.approx.f32 %0, %1;" : "=f"(r) : "f"(x)); return r;
}
__device__ __forceinline__ float sigm(float x) {
    return fmaf(tanha(x * 0.5f), 0.5f, 0.5f);
}

// One LSTM layer, 64 hidden, 64 batches per block (grid 128), 256 threads.
// Mapping: lane = hidden-pair a (j = 2a, 2a+1, all 4 gates), warp = 8 batches.
// Weights reordered in SMEM: wA[k][a] 16B = (i-pair, f-pair), wB = (g-pair, o-pair).
// Acts stored PLAIN float [KTOT][AST]; duplication into f32x2 done in registers.
template<int KIN>
__global__ void __launch_bounds__(256, 1) lstm_kernel(
    const float* __restrict__ inputs_main,
    const float* __restrict__ inputs_aux,
    const float* __restrict__ rnn1_mem,
    const float* __restrict__ Wi, const float* __restrict__ bi,
    const float* __restrict__ Whx1, const float* __restrict__ bhx1,  // Ws1/bs1 | Wt1/bt1
    const float* __restrict__ Whx2, const float* __restrict__ bhx2,  // Ws2/bs2 | Wt2/bt2
    const float* __restrict__ Wih, const float* __restrict__ Whh,
    const float* __restrict__ bih, const float* __restrict__ bhh,
    const float* __restrict__ Wso, const float* __restrict__ bso,
    float* __restrict__ out_sfc)
{
    constexpr bool IS1 = (KIN == 80);
    constexpr int KTOT = KIN + 64;
    constexpr int AST = 68; // act row stride in floats (16B-aligned rows, conflict-spread)

    extern __shared__ char smem_raw[];
    float* wAf  = (float*)smem_raw;                 // [KTOT][128] floats: per pair a: i0,i1,f0,f1
    float* wBf  = wAf + KTOT * 128;                 // g0,g1,o0,o1
    float* act  = wBf + KTOT * 128;                 // [KTOT][AST] plain floats
    ull*  sbias = (ull*)(act + KTOT * AST);         // [32 pairs][4 gates]
    float* sWi  = (float*)(sbias + 128);            // 256 (LSTM1)
    float* sbi  = sWi + 256;                        // 64  (LSTM1)

    const int tid  = threadIdx.x;
    const int lane = tid & 31;   // hidden-pair index a -> j = 2a, 2a+1
    const int w    = tid >> 5;   // warp -> batches 8w .. 8w+7
    const int b0   = blockIdx.x * 64;

    // ---- reorder weights: wA[k][a*4+q], q: 0=i_{2a} 1=i_{2a+1} 2=f_{2a} 3=f_{2a+1}; wB same for g,o
    for (int idx = tid; idx < KTOT * 256; idx += 256) {
        int k = idx >> 8, r = idx & 255;
        int half = r >> 7, rr = r & 127;
        int p = rr >> 2, q = rr & 3;
        int row = half * 128 + (q >> 1) * 64 + 2 * p + (q & 1);
        float v = (k < KIN) ? Wih[row * KIN + k] : Whh[row * 64 + (k - KIN)];
        (half ? wBf : wAf)[k * 128 + rr] = v;
    }
    if (tid < 128) {
        int a = tid >> 2, g = tid & 3;
        sbias[tid] = pk2(bih[g * 64 + 2 * a] + bhh[g * 64 + 2 * a],
                         bih[g * 64 + 2 * a + 1] + bhh[g * 64 + 2 * a + 1]);
    }
    if (IS1) {
        sWi[tid] = Wi[tid];
        if (tid < 64) sbi[tid] = bi[tid];
    }
    __syncthreads();

    // ---- initial h0 (plain float into act recurrent rows) and c0 (registers)
    float cst[8][2]; // [batch][e]
    #pragma unroll
    for (int e = 0; e < 2; e++) {
        const int j = 2 * lane + e;
        #pragma unroll
        for (int b = 0; b < 8; b++) {
            const int bb = b0 + 8 * w + b;
            float h0, c0;
            if (IS1) {
                float a0 = inputs_aux[bb * 3 + 0], a1 = inputs_aux[bb * 3 + 1], a2 = inputs_aux[bb * 3 + 2];
                h0 = tanha(a0 * Whx1[j * 3 + 0] + a1 * Whx1[j * 3 + 1] + a2 * Whx1[j * 3 + 2] + bhx1[j]);
                c0 = tanha(a0 * Whx2[j * 3 + 0] + a1 * Whx2[j * 3 + 1] + a2 * Whx2[j * 3 + 2] + bhx2[j]);
            } else {
                float toa = inputs_aux[bb * 3 + 1];
                h0 = toa * Whx1[j] + bhx1[j];
                c0 = toa * Whx2[j] + bhx2[j];
            }
            cst[b][e] = c0;
            act[(KIN + j) * AST + 8 * w + b] = h0;
        }
    }

    // ---- phase A for the first step (fill input rows)
    const int bA = tid & 63, kq = tid >> 6;
    {
        const int tf = IS1 ? (T_LEN - 1) : 0;
        if (IS1) {
            const float4 mv = *(const float4*)(inputs_main + ((size_t)(b0 + bA) * T_LEN + tf) * 4);
            #pragma unroll
            for (int kk = 0; kk < 16; kk++) {
                int k = kq * 16 + kk;
                act[k * AST + bA] = tanha(mv.x * sWi[k * 4] + mv.y * sWi[k * 4 + 1] +
                                          mv.z * sWi[k * 4 + 2] + mv.w * sWi[k * 4 + 3] + sbi[k]);
            }
            const float4 mm = *(const float4*)(rnn1_mem + (((size_t)(b0 + bA) * T_LEN + tf) * 16 + kq * 4));
            act[(64 + kq * 4 + 0) * AST + bA] = mm.x;
            act[(64 + kq * 4 + 1) * AST + bA] = mm.y;
            act[(64 + kq * 4 + 2) * AST + bA] = mm.z;
            act[(64 + kq * 4 + 3) * AST + bA] = mm.w;
        } else {
            #pragma unroll
            for (int it = 0; it < 16; it++) {
                int jj = it * 4 + kq;
                act[jj * AST + bA] = g_r1[((size_t)0 * 64 + jj) * B_TOT + b0 + bA];
            }
        }
    }
    __syncthreads();

    // ---- time loop
    for (int s = 0; s < T_LEN; s++) {
        const int t = IS1 ? (T_LEN - 1 - s) : s;

        ull aI[8], aF[8], aG[8], aO[8];
        {
            ull bI = sbias[lane * 4 + 0], bF = sbias[lane * 4 + 1];
            ull bG = sbias[lane * 4 + 2], bO = sbias[lane * 4 + 3];
            #pragma unroll
            for (int b = 0; b < 8; b++) { aI[b] = bI; aF[b] = bF; aG[b] = bG; aO[b] = bO; }
        }

        const float* wap = wAf + lane * 4;
        const float* wbp = wBf + lane * 4;
        const float* ap  = act + 8 * w;
        #pragma unroll 4
        for (int k = 0; k < KTOT; k++) {
            ulonglong2 wif = *(const ulonglong2*)(wap + k * 128);  // .x = i-pair, .y = f-pair
            ulonglong2 wgo = *(const ulonglong2*)(wbp + k * 128);  // .x = g-pair, .y = o-pair
            float4 x0 = *(const float4*)(ap + k * AST);            // batches 8w..8w+3 (uniform)
            float4 x1 = *(const float4*)(ap + k * AST + 4);        // batches 8w+4..8w+7
            ull d[8];
            d[0] = dup2(x0.x); d[1] = dup2(x0.y); d[2] = dup2(x0.z); d[3] = dup2(x0.w);
            d[4] = dup2(x1.x); d[5] = dup2(x1.y); d[6] = dup2(x1.z); d[7] = dup2(x1.w);
            #pragma unroll
            for (int b = 0; b < 8; b++) {
                fma2(aI[b], wif.x, d[b]);
                fma2(aF[b], wif.y, d[b]);
                fma2(aG[b], wgo.x, d[b]);
                fma2(aO[b], wgo.y, d[b]);
            }
        }
        __syncthreads();

        // prefetch next-step inputs (global) to hide latency under epilogue math
        const bool havenext = (s < T_LEN - 1);
        const int t2 = IS1 ? (t - 1) : (t + 1);
        float4 mv, mm;
        float rv[16];
        if (havenext) {
            if (IS1) {
                mv = *(const float4*)(inputs_main + ((size_t)(b0 + bA) * T_LEN + t2) * 4);
                mm = *(const float4*)(rnn1_mem + (((size_t)(b0 + bA) * T_LEN + t2) * 16 + kq * 4));
            } else {
                #pragma unroll
                for (int it = 0; it < 16; it++) {
                    int jj = it * 4 + kq;
                    rv[it] = g_r1[((size_t)t2 * 64 + jj) * B_TOT + b0 + bA];
                }
            }
        }

        // epilogue: gate activations, cell update
        float hv0[8], hv1[8];
        #pragma unroll
        for (int b = 0; b < 8; b++) {
            float2 gi = unpk(aI[b]);
            float2 gf = unpk(aF[b]);
            float2 gg = unpk(aG[b]);
            float2 go = unpk(aO[b]);
            float c0 = sigm(gf.x) * cst[b][0] + sigm(gi.x) * tanha(gg.x);
            cst[b][0] = c0;
            hv0[b] = sigm(go.x) * tanha(c0);
            float c1 = sigm(gf.y) * cst[b][1] + sigm(gi.y) * tanha(gg.y);
            cst[b][1] = c1;
            hv1[b] = sigm(go.y) * tanha(c1);
        }

        // write h: plain floats into act recurrent rows + transposed global (r1 / r2)
        const int j0 = 2 * lane;
        *(float4*)(act + (KIN + j0) * AST + 8 * w)         = make_float4(hv0[0], hv0[1], hv0[2], hv0[3]);
        *(float4*)(act + (KIN + j0) * AST + 8 * w + 4)     = make_float4(hv0[4], hv0[5], hv0[6], hv0[7]);
        *(float4*)(act + (KIN + j0 + 1) * AST + 8 * w)     = make_float4(hv1[0], hv1[1], hv1[2], hv1[3]);
        *(float4*)(act + (KIN + j0 + 1) * AST + 8 * w + 4) = make_float4(hv1[4], hv1[5], hv1[6], hv1[7]);
        {
            float* gp0 = g_r1 + ((size_t)t * 64 + j0) * B_TOT + b0 + 8 * w;
            float* gp1 = g_r1 + ((size_t)t * 64 + j0 + 1) * B_TOT + b0 + 8 * w;
            *(float4*)(gp0)     = make_float4(hv0[0], hv0[1], hv0[2], hv0[3]);
            *(float4*)(gp0 + 4) = make_float4(hv0[4], hv0[5], hv0[6], hv0[7]);
            *(float4*)(gp1)     = make_float4(hv1[0], hv1[1], hv1[2], hv1[3]);
            *(float4*)(gp1 + 4) = make_float4(hv1[4], hv1[5], hv1[6], hv1[7]);
        }

        // phase A: fill input rows for next step
        if (havenext) {
            if (IS1) {
                #pragma unroll
                for (int kk = 0; kk < 16; kk++) {
                    int k = kq * 16 + kk;
                    act[k * AST + bA] = tanha(mv.x * sWi[k * 4] + mv.y * sWi[k * 4 + 1] +
                                              mv.z * sWi[k * 4 + 2] + mv.w * sWi[k * 4 + 3] + sbi[k]);
                }
                act[(64 + kq * 4 + 0) * AST + bA] = mm.x;
                act[(64 + kq * 4 + 1) * AST + bA] = mm.y;
                act[(64 + kq * 4 + 2) * AST + bA] = mm.z;
                act[(64 + kq * 4 + 3) * AST + bA] = mm.w;
            } else {
                #pragma unroll
                for (int it = 0; it < 16; it++) {
                    int jj = it * 4 + kq;
                    act[jj * AST + bA] = rv[it];
                }
            }
        }
        __syncthreads();
    }

    // ---- out_sfc = hL @ Wso^T + bso (LSTM2 only; final h sits in act recurrent rows)
    if (!IS1) {
        if (tid < 64) {
            float s0 = bso[0], s1 = bso[1], s2 = bso[2];
            #pragma unroll 8
            for (int j = 0; j < 64; j++) {
                float h = act[(KIN + j) * AST + tid];
                s0 += Wso[0 * 64 + j] * h;
                s1 += Wso[1 * 64 + j] * h;
                s2 += Wso[2 * 64 + j] * h;
            }
            out_sfc[(size_t)(b0 + tid) * 3 + 0] = s0;
            out_sfc[(size_t)(b0 + tid) * 3 + 1] = s1;
            out_sfc[(size_t)(b0 + tid) * 3 + 2] = s2;
        }
    }
}

// lat = r2 @ Wl^T + bl ; new_mem = lat ; out = lat @ Wo^T + bo
__global__ void __launch_bounds__(256) head_kernel(
    const float* __restrict__ Wl, const float* __restrict__ bl,
    const float* __restrict__ Wo, const float* __restrict__ bo,
    float* __restrict__ out, float* __restrict__ newmem)
{
    __shared__ float sWl[1024], sbl[16], sWo[64], sbo[4];
    const int tid = threadIdx.x;
    for (int i = tid; i < 1024; i += 256) sWl[i] = Wl[i];
    if (tid < 16) sbl[tid] = bl[tid];
    if (tid < 64) sWo[tid] = Wo[tid];
    if (tid < 4)  sbo[tid] = bo[tid];
    __syncthreads();

    const int t = blockIdx.x;
    const size_t b = (size_t)blockIdx.y * 256 + tid;

    float lat[16];
    #pragma unroll
    for (int m = 0; m < 16; m++) lat[m] = sbl[m];

    // chunked over j to keep register pressure low
    #pragma unroll
    for (int c = 0; c < 4; c++) {
        float v[16];
        #pragma unroll
        for (int jj = 0; jj < 16; jj++)
            v[jj] = g_r1[((size_t)t * 64 + c * 16 + jj) * B_TOT + b];
        #pragma unroll
        for (int m = 0; m < 16; m++) {
            float s = lat[m];
            #pragma unroll
            for (int jj = 0; jj < 16; jj++)
                s += sWl[m * 64 + c * 16 + jj] * v[jj];
            lat[m] = s;
        }
    }

    float4* nm = (float4*)(newmem + (b * T_LEN + t) * 16);
    nm[0] = make_float4(lat[0], lat[1], lat[2], lat[3]);
    nm[1] = make_float4(lat[4], lat[5], lat[6], lat[7]);
    nm[2] = make_float4(lat[8], lat[9], lat[10], lat[11]);
    nm[3] = make_float4(lat[12], lat[13], lat[14], lat[15]);

    float o[4];
    #pragma unroll
    for (int y = 0; y < 4; y++) {
        float s = sbo[y];
        #pragma unroll
        for (int m = 0; m < 16; m++) s += sWo[y * 16 + m] * lat[m];
        o[y] = s;
    }
    *(float4*)(out + (b * T_LEN + t) * 4) = make_float4(o[0], o[1], o[2], o[3]);
}

extern "C" void kernel_launch(void* const* d_in, const int* in_sizes, int n_in,
                              void* d_out, int out_size) {
    const float* inputs_main = (const float*)d_in[0];
    const float* inputs_aux  = (const float*)d_in[1];
    const float* rnn1_mem    = (const float*)d_in[2];
    const float* Wi   = (const float*)d_in[3];
    const float* bi   = (const float*)d_in[4];
    const float* Ws1  = (const float*)d_in[5];
    const float* bs1  = (const float*)d_in[6];
    const float* Ws2  = (const float*)d_in[7];
    const float* bs2  = (const float*)d_in[8];
    const float* Wt1  = (const float*)d_in[9];
    const float* bt1  = (const float*)d_in[10];
    const float* Wt2  = (const float*)d_in[11];
    const float* bt2  = (const float*)d_in[12];
    const float* Wih1 = (const float*)d_in[13];
    const float* Whh1 = (const float*)d_in[14];
    const float* bih1 = (const float*)d_in[15];
    const float* bhh1 = (const float*)d_in[16];
    const float* Wih2 = (const float*)d_in[17];
    const float* Whh2 = (const float*)d_in[18];
    const float* bih2 = (const float*)d_in[19];
    const float* bhh2 = (const float*)d_in[20];
    const float* Wl   = (const float*)d_in[21];
    const float* bl   = (const float*)d_in[22];
    const float* Wo   = (const float*)d_in[23];
    const float* bo   = (const float*)d_in[24];
    const float* Wso  = (const float*)d_in[25];
    const float* bso  = (const float*)d_in[26];

    float* out     = (float*)d_out;
    float* out_sfc = out + (size_t)B_TOT * T_LEN * 4;
    float* newmem  = out_sfc + (size_t)B_TOT * 3;

    const int smem1 = 144 * 128 * 2 * 4 + 144 * 68 * 4 + 128 * 8 + (256 + 64) * 4;
    const int smem2 = 128 * 128 * 2 * 4 + 128 * 68 * 4 + 128 * 8 + (256 + 64) * 4;
    cudaFuncSetAttribute((const void*)lstm_kernel<80>, cudaFuncAttributeMaxDynamicSharedMemorySize, smem1);
    cudaFuncSetAttribute((const void*)lstm_kernel<64>, cudaFuncAttributeMaxDynamicSharedMemorySize, smem2);

    lstm_kernel<80><<<128, 256, smem1>>>(inputs_main, inputs_aux, rnn1_mem, Wi, bi,
                                         Ws1, bs1, Ws2, bs2, Wih1, Whh1, bih1, bhh1,
                                         nullptr, nullptr, nullptr);
    lstm_kernel<64><<<128, 256, smem2>>>(inputs_main, inputs_aux, rnn1_mem, Wi, bi,
                                         Wt1, bt1, Wt2, bt2, Wih2, Whh2, bih2, bhh2,
                                         Wso, bso, out_sfc);
    head_kernel<<<dim3(T_LEN, B_TOT / 256), 256>>>(Wl, bl, Wo, bo, out, newmem);
}